// round 6
// baseline (speedup 1.0000x reference)
#include <cuda_runtime.h>
#include <cuda_bf16.h>
#include <cstdint>

// Causal attention B=16, N=2048, D=256 fp32, via mma.sync bf16 3-term split
// (sm_100 non-'a': no tcgen05; Ampere-path HMMA + ldmatrix + cp.async).
//
// R5: 16 warps (512 thr) per CTA; finer S/PV split (4 warps/SMSP) to hide
// MMA dependency + ldsm latency. Same tiles, numerics, cp.async pipeline.

#define NSEQ  2048
#define DH    256
#define BATCH 16
#define BQ    64
#define BK    64
#define NELEM (BATCH*NSEQ*DH)
#define NTHR  512

__device__ __nv_bfloat16 g_qhi[NELEM];
__device__ __nv_bfloat16 g_qlo[NELEM];
__device__ __nv_bfloat16 g_khi[NELEM];
__device__ __nv_bfloat16 g_klo[NELEM];
__device__ __nv_bfloat16 g_vhi[NELEM];
__device__ __nv_bfloat16 g_vlo[NELEM];

// ---- smem byte offsets ----
#define O_QHI 0
#define O_QLO 32768
#define O_KHI 65536
#define O_KLO 98304
#define O_VHI 131072
#define O_VLO 163840
#define O_PHI 196608
#define O_PLO 204800
#define O_PM  212992
#define O_LR  213248
#define SMEM_TOTAL 214272

__device__ __forceinline__ uint32_t smem_u32(const void* p){
    uint32_t a; asm("{ .reg .u64 t; cvta.to.shared.u64 t, %1; cvt.u32.u64 %0, t; }":"=r"(a):"l"(p)); return a;
}
__device__ __forceinline__ void ldsm4(uint32_t a, uint32_t r[4]){
    asm volatile("ldmatrix.sync.aligned.m8n8.x4.shared.b16 {%0,%1,%2,%3},[%4];"
                 :"=r"(r[0]),"=r"(r[1]),"=r"(r[2]),"=r"(r[3]):"r"(a));
}
__device__ __forceinline__ void ldsm4t(uint32_t a, uint32_t r[4]){
    asm volatile("ldmatrix.sync.aligned.m8n8.x4.trans.shared.b16 {%0,%1,%2,%3},[%4];"
                 :"=r"(r[0]),"=r"(r[1]),"=r"(r[2]),"=r"(r[3]):"r"(a));
}
__device__ __forceinline__ void mma16816(float c[4], const uint32_t a[4], uint32_t b0, uint32_t b1){
    asm volatile("mma.sync.aligned.m16n8k16.row.col.f32.bf16.bf16.f32 "
                 "{%0,%1,%2,%3},{%4,%5,%6,%7},{%8,%9},{%0,%1,%2,%3};"
                 :"+f"(c[0]),"+f"(c[1]),"+f"(c[2]),"+f"(c[3])
                 :"r"(a[0]),"r"(a[1]),"r"(a[2]),"r"(a[3]),"r"(b0),"r"(b1));
}
__device__ __forceinline__ void cpa16(uint32_t dst, const void* src){
    asm volatile("cp.async.cg.shared.global [%0],[%1],16;"::"r"(dst),"l"(src):"memory");
}
#define CP_COMMIT() asm volatile("cp.async.commit_group;":::"memory")
#define CP_WAIT(n)  asm volatile("cp.async.wait_group %0;"::"n"(n):"memory")

__device__ __forceinline__ uint32_t pack2(float a, float b){
    __nv_bfloat162 h; h.x=__float2bfloat16(a); h.y=__float2bfloat16(b);
    return *reinterpret_cast<uint32_t*>(&h);
}
__device__ __forceinline__ uint32_t pack_hi2(float a, float b, float& ra, float& rb){
    __nv_bfloat16 ha=__float2bfloat16(a), hb=__float2bfloat16(b);
    ra = a - __bfloat162float(ha); rb = b - __bfloat162float(hb);
    __nv_bfloat162 h; h.x=ha; h.y=hb;
    return *reinterpret_cast<uint32_t*>(&h);
}

// ---- pass 1: fp32 -> bf16 hi/lo ----
__global__ void cvt_kernel(const float* __restrict__ Q, const float* __restrict__ K,
                           const float* __restrict__ V)
{
    int i = blockIdx.x*blockDim.x + threadIdx.x;
    float4 q = ((const float4*)Q)[i];
    q.x*=0.0625f; q.y*=0.0625f; q.z*=0.0625f; q.w*=0.0625f;
    float l0,l1,l2,l3;
    uint32_t h01,h23;
    h01 = pack_hi2(q.x,q.y,l0,l1); h23 = pack_hi2(q.z,q.w,l2,l3);
    ((uint32_t*)g_qhi)[2*i]=h01; ((uint32_t*)g_qhi)[2*i+1]=h23;
    ((uint32_t*)g_qlo)[2*i]=pack2(l0,l1); ((uint32_t*)g_qlo)[2*i+1]=pack2(l2,l3);
    float4 k = ((const float4*)K)[i];
    h01 = pack_hi2(k.x,k.y,l0,l1); h23 = pack_hi2(k.z,k.w,l2,l3);
    ((uint32_t*)g_khi)[2*i]=h01; ((uint32_t*)g_khi)[2*i+1]=h23;
    ((uint32_t*)g_klo)[2*i]=pack2(l0,l1); ((uint32_t*)g_klo)[2*i+1]=pack2(l2,l3);
    float4 v = ((const float4*)V)[i];
    h01 = pack_hi2(v.x,v.y,l0,l1); h23 = pack_hi2(v.z,v.w,l2,l3);
    ((uint32_t*)g_vhi)[2*i]=h01; ((uint32_t*)g_vhi)[2*i+1]=h23;
    ((uint32_t*)g_vlo)[2*i]=pack2(l0,l1); ((uint32_t*)g_vlo)[2*i+1]=pack2(l2,l3);
}

// cp.async one 64x256 bf16 tile (row stride 512B, 32 chunks of 16B, XOR swizzle)
__device__ __forceinline__ void load_tile(uint32_t smb, uint32_t off,
                                          const __nv_bfloat16* gsrc, int tid)
{
    const char* gs = (const char*)gsrc;
    #pragma unroll
    for (int it=0; it<4; ++it){
        int cid = tid + it*NTHR;
        int row = cid >> 5, c = cid & 31;
        uint32_t dst = smb + off + row*512 + (((uint32_t)(c ^ (row&7)))<<4);
        cpa16(dst, gs + row*512 + c*16);
    }
}

__global__ __launch_bounds__(NTHR,1)
void fa_mma_kernel(const int* __restrict__ PMg, float* __restrict__ Og)
{
    extern __shared__ char sm[];
    const uint32_t smb = smem_u32(sm);
    const int tid=threadIdx.x, lane=tid&31, wid=tid>>5;
    const int rb = wid & 3, ch = wid >> 2;   // ch in 0..3 (S cols / O cols group)
    const int qt = (int)gridDim.x-1-(int)blockIdx.x;
    const int b  = blockIdx.y;
    const int qbase = qt*BQ;

    const size_t base = (size_t)b*NSEQ*DH;

    // ---- prologue: group0 = Q + K(0), group1 = V(0) ----
    load_tile(smb, O_QHI, g_qhi + base + (size_t)qbase*DH, tid);
    load_tile(smb, O_QLO, g_qlo + base + (size_t)qbase*DH, tid);
    load_tile(smb, O_KHI, g_khi + base, tid);
    load_tile(smb, O_KLO, g_klo + base, tid);
    CP_COMMIT();
    load_tile(smb, O_VHI, g_vhi + base, tid);
    load_tile(smb, O_VLO, g_vlo + base, tid);
    CP_COMMIT();
    if (tid < BK)
        ((float*)(sm+O_PM))[tid] = PMg[(size_t)b*NSEQ + tid] ? 1.f : 0.f;
    CP_WAIT(1);                      // Q + K(0) ready
    __syncthreads();

    // ldmatrix per-lane geometry
    const int rowA = rb*16 + (lane & 15);
    const int ahl  = lane >> 4;
    const int rxa  = rowA & 7;
    const uint32_t aQhi = smb + O_QHI + rowA*512;
    const uint32_t aQlo = smb + O_QLO + rowA*512;
    const uint32_t aPhi = smb + O_PHI + rowA*128;
    const uint32_t aPlo = smb + O_PLO + rowA*128;

    const int rowB = (lane & 7) + ((lane >> 4) << 3);   // K row within 16-group
    const int bhl  = (lane >> 3) & 1;
    const int rxb  = rowB & 7;
    const uint32_t bKhi = smb + O_KHI + (ch*16 + rowB)*512;
    const uint32_t bKlo = smb + O_KLO + (ch*16 + rowB)*512;

    const int rowV = (lane & 7) + (((lane >> 3) & 1) << 3);
    const int vhl  = lane >> 4;
    const int rxv  = rowV & 7;
    const uint32_t bVhi = smb + O_VHI + rowV*512;
    const uint32_t bVlo = smb + O_VLO + rowV*512;

    float o[8][4];
    #pragma unroll
    for (int n=0;n<8;++n){ o[n][0]=0.f;o[n][1]=0.f;o[n][2]=0.f;o[n][3]=0.f; }
    float lsum0=0.f, lsum1=0.f;

    for (int kt=0; kt<=qt; ++kt){
        const int kbase = kt*BK;
        const bool more = (kt < qt);

        // ---- S = Q K^T (rows rb*16.., cols ch*16..) ----
        float sacc[2][4];
        #pragma unroll
        for (int j=0;j<2;++j){ sacc[j][0]=0.f;sacc[j][1]=0.f;sacc[j][2]=0.f;sacc[j][3]=0.f; }

        for (int ks=0; ks<16; ++ks){
            uint32_t a_hi[4], a_lo[4], bh[4], bl[4];
            {
                uint32_t swa = (uint32_t)((ks*2 + ahl) ^ rxa) << 4;
                ldsm4(aQhi + swa, a_hi);
                ldsm4(aQlo + swa, a_lo);
                uint32_t swb = (uint32_t)((ks*2 + bhl) ^ rxb) << 4;
                ldsm4(bKhi + swb, bh);
                ldsm4(bKlo + swb, bl);
            }
            mma16816(sacc[0], a_hi, bh[0], bh[1]);
            mma16816(sacc[1], a_hi, bh[2], bh[3]);
            mma16816(sacc[0], a_lo, bh[0], bh[1]);
            mma16816(sacc[1], a_lo, bh[2], bh[3]);
            mma16816(sacc[0], a_hi, bl[0], bl[1]);
            mma16816(sacc[1], a_hi, bl[2], bl[3]);
        }

        // ---- epilogue: P = exp(S)*pad*(causal on diagonal tile) ----
        const float* pmv = (const float*)(sm + O_PM);
        const bool diag = (kt == qt);
        const int r0g = qbase + rb*16 + (lane>>2);
        float rs0 = 0.f, rs1 = 0.f;
        const int rloc = rb*16 + (lane>>2);
        #pragma unroll
        for (int j=0;j<2;++j){
            int c0 = ch*16 + j*8 + (lane&3)*2;
            float m0 = pmv[c0], m1 = pmv[c0+1];
            int gc0 = kbase + c0;
            float v0 = __expf(sacc[j][0]) * m0;
            float v1 = __expf(sacc[j][1]) * m1;
            float v2 = __expf(sacc[j][2]) * m0;
            float v3 = __expf(sacc[j][3]) * m1;
            if (diag){
                if (gc0   > r0g)   v0 = 0.f;
                if (gc0+1 > r0g)   v1 = 0.f;
                if (gc0   > r0g+8) v2 = 0.f;
                if (gc0+1 > r0g+8) v3 = 0.f;
            }
            rs0 += v0 + v1;  rs1 += v2 + v3;
            float l0,l1;
            uint32_t hA = pack_hi2(v0,v1,l0,l1);
            uint32_t lA = pack2(l0,l1);
            uint32_t hB = pack_hi2(v2,v3,l0,l1);
            uint32_t lB = pack2(l0,l1);
            int chunk = ch*2 + j;
            uint32_t sw  = (uint32_t)((chunk ^ (rloc&7))<<4) + (lane&3)*4;
            uint32_t o0 = rloc*128 + sw;
            uint32_t o2 = (rloc+8)*128 + sw;
            *(uint32_t*)(sm + O_PHI + o0) = hA;
            *(uint32_t*)(sm + O_PLO + o0) = lA;
            *(uint32_t*)(sm + O_PHI + o2) = hB;
            *(uint32_t*)(sm + O_PLO + o2) = lB;
        }
        rs0 += __shfl_xor_sync(0xffffffffu, rs0, 1);
        rs0 += __shfl_xor_sync(0xffffffffu, rs0, 2);
        rs1 += __shfl_xor_sync(0xffffffffu, rs1, 1);
        rs1 += __shfl_xor_sync(0xffffffffu, rs1, 2);
        lsum0 += rs0;  lsum1 += rs1;

        __syncthreads();   // P visible; all warps done reading K(kt)

        // ---- issue K(kt+1) (overlaps PV); refill PM for kt+1 ----
        if (more){
            const size_t nk = base + (size_t)(kbase+BK)*DH;
            load_tile(smb, O_KHI, g_khi + nk, tid);
            load_tile(smb, O_KLO, g_klo + nk, tid);
            CP_COMMIT();
            if (tid < BK)
                ((float*)(sm+O_PM))[tid] =
                    PMg[(size_t)b*NSEQ + kbase + BK + tid] ? 1.f : 0.f;
        }

        // ---- wait V(kt) ----
        if (more) { CP_WAIT(1); } else { CP_WAIT(0); }
        __syncthreads();   // V visible to all warps

        // ---- O += P V (rows rb*16.., cols ch*64..) ----
        for (int kks=0; kks<4; ++kks){
            uint32_t pa_hi[4], pa_lo[4];
            {
                uint32_t sw = (uint32_t)((kks*2 + ahl) ^ rxa) << 4;
                ldsm4(aPhi + sw, pa_hi);
                ldsm4(aPlo + sw, pa_lo);
            }
            uint32_t vrow = (uint32_t)((kks*16)*512);
            #pragma unroll
            for (int ncp=0; ncp<4; ++ncp){
                uint32_t vh[4], vl[4];
                uint32_t sw = (uint32_t)(((ch*8 + ncp*2 + vhl) ^ rxv) << 4);
                ldsm4t(bVhi + vrow + sw, vh);
                ldsm4t(bVlo + vrow + sw, vl);
                mma16816(o[2*ncp],   pa_hi, vh[0], vh[1]);
                mma16816(o[2*ncp+1], pa_hi, vh[2], vh[3]);
                mma16816(o[2*ncp],   pa_lo, vh[0], vh[1]);
                mma16816(o[2*ncp+1], pa_lo, vh[2], vh[3]);
                mma16816(o[2*ncp],   pa_hi, vl[0], vl[1]);
                mma16816(o[2*ncp+1], pa_hi, vl[2], vl[3]);
            }
        }

        // ---- issue V(kt+1) (overlaps next S-MMA); then wait K(kt+1) ----
        if (more){
            __syncthreads();   // all PV reads of V(kt) done
            const size_t nk = base + (size_t)(kbase+BK)*DH;
            load_tile(smb, O_VHI, g_vhi + nk, tid);
            load_tile(smb, O_VLO, g_vlo + nk, tid);
            CP_COMMIT();
            CP_WAIT(1);        // K(kt+1) ready (older than V(kt+1))
            __syncthreads();
        }
    }

    // ---- combine row sums across 4 col-groups ----
    float* lr = (float*)(sm + O_LR);
    if ((lane & 3) == 0){
        lr[ch*64 + rb*16 + (lane>>2)]     = lsum0;
        lr[ch*64 + rb*16 + (lane>>2) + 8] = lsum1;
    }
    __syncthreads();
    const int r0 = rb*16 + (lane>>2);
    const float inv0 = 1.0f/(lr[r0] + lr[64+r0] + lr[128+r0] + lr[192+r0]);
    const float inv1 = 1.0f/(lr[r0+8] + lr[64+r0+8] + lr[128+r0+8] + lr[192+r0+8]);

    // ---- write O (cols ch*64..) ----
    float* orow0 = Og + ((size_t)b*NSEQ + qbase + r0)*DH     + ch*64 + (lane&3)*2;
    float* orow1 = Og + ((size_t)b*NSEQ + qbase + r0 + 8)*DH + ch*64 + (lane&3)*2;
    #pragma unroll
    for (int nc=0; nc<8; ++nc){
        float2 w0; w0.x = o[nc][0]*inv0; w0.y = o[nc][1]*inv0;
        float2 w1; w1.x = o[nc][2]*inv1; w1.y = o[nc][3]*inv1;
        *(float2*)(orow0 + nc*8) = w0;
        *(float2*)(orow1 + nc*8) = w1;
    }
}

extern "C" void kernel_launch(void* const* d_in, const int* in_sizes, int n_in,
                              void* d_out, int out_size)
{
    const float* Q  = (const float*)d_in[0];
    const float* K  = (const float*)d_in[1];
    const float* V  = (const float*)d_in[2];
    const int*   PM = (const int*)d_in[3];
    float*       O  = (float*)d_out;

    cvt_kernel<<<NELEM/4/256, 256>>>(Q, K, V);

    cudaFuncSetAttribute(fa_mma_kernel,
                         cudaFuncAttributeMaxDynamicSharedMemorySize, SMEM_TOTAL);
    dim3 grid(NSEQ/BQ, BATCH);
    fa_mma_kernel<<<grid, NTHR, SMEM_TOTAL>>>(PM, O);
}

// round 7
// speedup vs baseline: 1.0007x; 1.0007x over previous
#include <cuda_runtime.h>
#include <cuda_bf16.h>
#include <cstdint>

// Causal attention B=16, N=2048, D=256 fp32, via mma.sync bf16 3-term split
// (sm_100 non-'a': no tcgen05; Ampere-path HMMA + ldmatrix + cp.async).
//
// R5: 16 warps (512 thr) per CTA; finer S/PV split (4 warps/SMSP) to hide
// MMA dependency + ldsm latency. Same tiles, numerics, cp.async pipeline.

#define NSEQ  2048
#define DH    256
#define BATCH 16
#define BQ    64
#define BK    64
#define NELEM (BATCH*NSEQ*DH)
#define NTHR  512

__device__ __nv_bfloat16 g_qhi[NELEM];
__device__ __nv_bfloat16 g_qlo[NELEM];
__device__ __nv_bfloat16 g_khi[NELEM];
__device__ __nv_bfloat16 g_klo[NELEM];
__device__ __nv_bfloat16 g_vhi[NELEM];
__device__ __nv_bfloat16 g_vlo[NELEM];

// ---- smem byte offsets ----
#define O_QHI 0
#define O_QLO 32768
#define O_KHI 65536
#define O_KLO 98304
#define O_VHI 131072
#define O_VLO 163840
#define O_PHI 196608
#define O_PLO 204800
#define O_PM  212992
#define O_LR  213248
#define SMEM_TOTAL 214272

__device__ __forceinline__ uint32_t smem_u32(const void* p){
    uint32_t a; asm("{ .reg .u64 t; cvta.to.shared.u64 t, %1; cvt.u32.u64 %0, t; }":"=r"(a):"l"(p)); return a;
}
__device__ __forceinline__ void ldsm4(uint32_t a, uint32_t r[4]){
    asm volatile("ldmatrix.sync.aligned.m8n8.x4.shared.b16 {%0,%1,%2,%3},[%4];"
                 :"=r"(r[0]),"=r"(r[1]),"=r"(r[2]),"=r"(r[3]):"r"(a));
}
__device__ __forceinline__ void ldsm4t(uint32_t a, uint32_t r[4]){
    asm volatile("ldmatrix.sync.aligned.m8n8.x4.trans.shared.b16 {%0,%1,%2,%3},[%4];"
                 :"=r"(r[0]),"=r"(r[1]),"=r"(r[2]),"=r"(r[3]):"r"(a));
}
__device__ __forceinline__ void mma16816(float c[4], const uint32_t a[4], uint32_t b0, uint32_t b1){
    asm volatile("mma.sync.aligned.m16n8k16.row.col.f32.bf16.bf16.f32 "
                 "{%0,%1,%2,%3},{%4,%5,%6,%7},{%8,%9},{%0,%1,%2,%3};"
                 :"+f"(c[0]),"+f"(c[1]),"+f"(c[2]),"+f"(c[3])
                 :"r"(a[0]),"r"(a[1]),"r"(a[2]),"r"(a[3]),"r"(b0),"r"(b1));
}
__device__ __forceinline__ void cpa16(uint32_t dst, const void* src){
    asm volatile("cp.async.cg.shared.global [%0],[%1],16;"::"r"(dst),"l"(src):"memory");
}
#define CP_COMMIT() asm volatile("cp.async.commit_group;":::"memory")
#define CP_WAIT(n)  asm volatile("cp.async.wait_group %0;"::"n"(n):"memory")

__device__ __forceinline__ uint32_t pack2(float a, float b){
    __nv_bfloat162 h; h.x=__float2bfloat16(a); h.y=__float2bfloat16(b);
    return *reinterpret_cast<uint32_t*>(&h);
}
__device__ __forceinline__ uint32_t pack_hi2(float a, float b, float& ra, float& rb){
    __nv_bfloat16 ha=__float2bfloat16(a), hb=__float2bfloat16(b);
    ra = a - __bfloat162float(ha); rb = b - __bfloat162float(hb);
    __nv_bfloat162 h; h.x=ha; h.y=hb;
    return *reinterpret_cast<uint32_t*>(&h);
}

// ---- pass 1: fp32 -> bf16 hi/lo ----
__global__ void cvt_kernel(const float* __restrict__ Q, const float* __restrict__ K,
                           const float* __restrict__ V)
{
    int i = blockIdx.x*blockDim.x + threadIdx.x;
    float4 q = ((const float4*)Q)[i];
    q.x*=0.0625f; q.y*=0.0625f; q.z*=0.0625f; q.w*=0.0625f;
    float l0,l1,l2,l3;
    uint32_t h01,h23;
    h01 = pack_hi2(q.x,q.y,l0,l1); h23 = pack_hi2(q.z,q.w,l2,l3);
    ((uint32_t*)g_qhi)[2*i]=h01; ((uint32_t*)g_qhi)[2*i+1]=h23;
    ((uint32_t*)g_qlo)[2*i]=pack2(l0,l1); ((uint32_t*)g_qlo)[2*i+1]=pack2(l2,l3);
    float4 k = ((const float4*)K)[i];
    h01 = pack_hi2(k.x,k.y,l0,l1); h23 = pack_hi2(k.z,k.w,l2,l3);
    ((uint32_t*)g_khi)[2*i]=h01; ((uint32_t*)g_khi)[2*i+1]=h23;
    ((uint32_t*)g_klo)[2*i]=pack2(l0,l1); ((uint32_t*)g_klo)[2*i+1]=pack2(l2,l3);
    float4 v = ((const float4*)V)[i];
    h01 = pack_hi2(v.x,v.y,l0,l1); h23 = pack_hi2(v.z,v.w,l2,l3);
    ((uint32_t*)g_vhi)[2*i]=h01; ((uint32_t*)g_vhi)[2*i+1]=h23;
    ((uint32_t*)g_vlo)[2*i]=pack2(l0,l1); ((uint32_t*)g_vlo)[2*i+1]=pack2(l2,l3);
}

// cp.async one 64x256 bf16 tile (row stride 512B, 32 chunks of 16B, XOR swizzle)
__device__ __forceinline__ void load_tile(uint32_t smb, uint32_t off,
                                          const __nv_bfloat16* gsrc, int tid)
{
    const char* gs = (const char*)gsrc;
    #pragma unroll
    for (int it=0; it<4; ++it){
        int cid = tid + it*NTHR;
        int row = cid >> 5, c = cid & 31;
        uint32_t dst = smb + off + row*512 + (((uint32_t)(c ^ (row&7)))<<4);
        cpa16(dst, gs + row*512 + c*16);
    }
}

__global__ __launch_bounds__(NTHR,1)
void fa_mma_kernel(const int* __restrict__ PMg, float* __restrict__ Og)
{
    extern __shared__ char sm[];
    const uint32_t smb = smem_u32(sm);
    const int tid=threadIdx.x, lane=tid&31, wid=tid>>5;
    const int rb = wid & 3, ch = wid >> 2;   // ch in 0..3 (S cols / O cols group)
    const int qt = (int)gridDim.x-1-(int)blockIdx.x;
    const int b  = blockIdx.y;
    const int qbase = qt*BQ;

    const size_t base = (size_t)b*NSEQ*DH;

    // ---- prologue: group0 = Q + K(0), group1 = V(0) ----
    load_tile(smb, O_QHI, g_qhi + base + (size_t)qbase*DH, tid);
    load_tile(smb, O_QLO, g_qlo + base + (size_t)qbase*DH, tid);
    load_tile(smb, O_KHI, g_khi + base, tid);
    load_tile(smb, O_KLO, g_klo + base, tid);
    CP_COMMIT();
    load_tile(smb, O_VHI, g_vhi + base, tid);
    load_tile(smb, O_VLO, g_vlo + base, tid);
    CP_COMMIT();
    if (tid < BK)
        ((float*)(sm+O_PM))[tid] = PMg[(size_t)b*NSEQ + tid] ? 1.f : 0.f;
    CP_WAIT(1);                      // Q + K(0) ready
    __syncthreads();

    // ldmatrix per-lane geometry
    const int rowA = rb*16 + (lane & 15);
    const int ahl  = lane >> 4;
    const int rxa  = rowA & 7;
    const uint32_t aQhi = smb + O_QHI + rowA*512;
    const uint32_t aQlo = smb + O_QLO + rowA*512;
    const uint32_t aPhi = smb + O_PHI + rowA*128;
    const uint32_t aPlo = smb + O_PLO + rowA*128;

    const int rowB = (lane & 7) + ((lane >> 4) << 3);   // K row within 16-group
    const int bhl  = (lane >> 3) & 1;
    const int rxb  = rowB & 7;
    const uint32_t bKhi = smb + O_KHI + (ch*16 + rowB)*512;
    const uint32_t bKlo = smb + O_KLO + (ch*16 + rowB)*512;

    const int rowV = (lane & 7) + (((lane >> 3) & 1) << 3);
    const int vhl  = lane >> 4;
    const int rxv  = rowV & 7;
    const uint32_t bVhi = smb + O_VHI + rowV*512;
    const uint32_t bVlo = smb + O_VLO + rowV*512;

    float o[8][4];
    #pragma unroll
    for (int n=0;n<8;++n){ o[n][0]=0.f;o[n][1]=0.f;o[n][2]=0.f;o[n][3]=0.f; }
    float lsum0=0.f, lsum1=0.f;

    for (int kt=0; kt<=qt; ++kt){
        const int kbase = kt*BK;
        const bool more = (kt < qt);

        // ---- S = Q K^T (rows rb*16.., cols ch*16..) ----
        float sacc[2][4];
        #pragma unroll
        for (int j=0;j<2;++j){ sacc[j][0]=0.f;sacc[j][1]=0.f;sacc[j][2]=0.f;sacc[j][3]=0.f; }

        for (int ks=0; ks<16; ++ks){
            uint32_t a_hi[4], a_lo[4], bh[4], bl[4];
            {
                uint32_t swa = (uint32_t)((ks*2 + ahl) ^ rxa) << 4;
                ldsm4(aQhi + swa, a_hi);
                ldsm4(aQlo + swa, a_lo);
                uint32_t swb = (uint32_t)((ks*2 + bhl) ^ rxb) << 4;
                ldsm4(bKhi + swb, bh);
                ldsm4(bKlo + swb, bl);
            }
            mma16816(sacc[0], a_hi, bh[0], bh[1]);
            mma16816(sacc[1], a_hi, bh[2], bh[3]);
            mma16816(sacc[0], a_lo, bh[0], bh[1]);
            mma16816(sacc[1], a_lo, bh[2], bh[3]);
            mma16816(sacc[0], a_hi, bl[0], bl[1]);
            mma16816(sacc[1], a_hi, bl[2], bl[3]);
        }

        // ---- epilogue: P = exp(S)*pad*(causal on diagonal tile) ----
        const float* pmv = (const float*)(sm + O_PM);
        const bool diag = (kt == qt);
        const int r0g = qbase + rb*16 + (lane>>2);
        float rs0 = 0.f, rs1 = 0.f;
        const int rloc = rb*16 + (lane>>2);
        #pragma unroll
        for (int j=0;j<2;++j){
            int c0 = ch*16 + j*8 + (lane&3)*2;
            float m0 = pmv[c0], m1 = pmv[c0+1];
            int gc0 = kbase + c0;
            float v0 = __expf(sacc[j][0]) * m0;
            float v1 = __expf(sacc[j][1]) * m1;
            float v2 = __expf(sacc[j][2]) * m0;
            float v3 = __expf(sacc[j][3]) * m1;
            if (diag){
                if (gc0   > r0g)   v0 = 0.f;
                if (gc0+1 > r0g)   v1 = 0.f;
                if (gc0   > r0g+8) v2 = 0.f;
                if (gc0+1 > r0g+8) v3 = 0.f;
            }
            rs0 += v0 + v1;  rs1 += v2 + v3;
            float l0,l1;
            uint32_t hA = pack_hi2(v0,v1,l0,l1);
            uint32_t lA = pack2(l0,l1);
            uint32_t hB = pack_hi2(v2,v3,l0,l1);
            uint32_t lB = pack2(l0,l1);
            int chunk = ch*2 + j;
            uint32_t sw  = (uint32_t)((chunk ^ (rloc&7))<<4) + (lane&3)*4;
            uint32_t o0 = rloc*128 + sw;
            uint32_t o2 = (rloc+8)*128 + sw;
            *(uint32_t*)(sm + O_PHI + o0) = hA;
            *(uint32_t*)(sm + O_PLO + o0) = lA;
            *(uint32_t*)(sm + O_PHI + o2) = hB;
            *(uint32_t*)(sm + O_PLO + o2) = lB;
        }
        rs0 += __shfl_xor_sync(0xffffffffu, rs0, 1);
        rs0 += __shfl_xor_sync(0xffffffffu, rs0, 2);
        rs1 += __shfl_xor_sync(0xffffffffu, rs1, 1);
        rs1 += __shfl_xor_sync(0xffffffffu, rs1, 2);
        lsum0 += rs0;  lsum1 += rs1;

        __syncthreads();   // P visible; all warps done reading K(kt)

        // ---- issue K(kt+1) (overlaps PV); refill PM for kt+1 ----
        if (more){
            const size_t nk = base + (size_t)(kbase+BK)*DH;
            load_tile(smb, O_KHI, g_khi + nk, tid);
            load_tile(smb, O_KLO, g_klo + nk, tid);
            CP_COMMIT();
            if (tid < BK)
                ((float*)(sm+O_PM))[tid] =
                    PMg[(size_t)b*NSEQ + kbase + BK + tid] ? 1.f : 0.f;
        }

        // ---- wait V(kt) ----
        if (more) { CP_WAIT(1); } else { CP_WAIT(0); }
        __syncthreads();   // V visible to all warps

        // ---- O += P V (rows rb*16.., cols ch*64..) ----
        for (int kks=0; kks<4; ++kks){
            uint32_t pa_hi[4], pa_lo[4];
            {
                uint32_t sw = (uint32_t)((kks*2 + ahl) ^ rxa) << 4;
                ldsm4(aPhi + sw, pa_hi);
                ldsm4(aPlo + sw, pa_lo);
            }
            uint32_t vrow = (uint32_t)((kks*16)*512);
            #pragma unroll
            for (int ncp=0; ncp<4; ++ncp){
                uint32_t vh[4], vl[4];
                uint32_t sw = (uint32_t)(((ch*8 + ncp*2 + vhl) ^ rxv) << 4);
                ldsm4t(bVhi + vrow + sw, vh);
                ldsm4t(bVlo + vrow + sw, vl);
                mma16816(o[2*ncp],   pa_hi, vh[0], vh[1]);
                mma16816(o[2*ncp+1], pa_hi, vh[2], vh[3]);
                mma16816(o[2*ncp],   pa_lo, vh[0], vh[1]);
                mma16816(o[2*ncp+1], pa_lo, vh[2], vh[3]);
                mma16816(o[2*ncp],   pa_hi, vl[0], vl[1]);
                mma16816(o[2*ncp+1], pa_hi, vl[2], vl[3]);
            }
        }

        // ---- issue V(kt+1) (overlaps next S-MMA); then wait K(kt+1) ----
        if (more){
            __syncthreads();   // all PV reads of V(kt) done
            const size_t nk = base + (size_t)(kbase+BK)*DH;
            load_tile(smb, O_VHI, g_vhi + nk, tid);
            load_tile(smb, O_VLO, g_vlo + nk, tid);
            CP_COMMIT();
            CP_WAIT(1);        // K(kt+1) ready (older than V(kt+1))
            __syncthreads();
        }
    }

    // ---- combine row sums across 4 col-groups ----
    float* lr = (float*)(sm + O_LR);
    if ((lane & 3) == 0){
        lr[ch*64 + rb*16 + (lane>>2)]     = lsum0;
        lr[ch*64 + rb*16 + (lane>>2) + 8] = lsum1;
    }
    __syncthreads();
    const int r0 = rb*16 + (lane>>2);
    const float inv0 = 1.0f/(lr[r0] + lr[64+r0] + lr[128+r0] + lr[192+r0]);
    const float inv1 = 1.0f/(lr[r0+8] + lr[64+r0+8] + lr[128+r0+8] + lr[192+r0+8]);

    // ---- write O (cols ch*64..) ----
    float* orow0 = Og + ((size_t)b*NSEQ + qbase + r0)*DH     + ch*64 + (lane&3)*2;
    float* orow1 = Og + ((size_t)b*NSEQ + qbase + r0 + 8)*DH + ch*64 + (lane&3)*2;
    #pragma unroll
    for (int nc=0; nc<8; ++nc){
        float2 w0; w0.x = o[nc][0]*inv0; w0.y = o[nc][1]*inv0;
        float2 w1; w1.x = o[nc][2]*inv1; w1.y = o[nc][3]*inv1;
        *(float2*)(orow0 + nc*8) = w0;
        *(float2*)(orow1 + nc*8) = w1;
    }
}

extern "C" void kernel_launch(void* const* d_in, const int* in_sizes, int n_in,
                              void* d_out, int out_size)
{
    const float* Q  = (const float*)d_in[0];
    const float* K  = (const float*)d_in[1];
    const float* V  = (const float*)d_in[2];
    const int*   PM = (const int*)d_in[3];
    float*       O  = (float*)d_out;

    cvt_kernel<<<NELEM/4/256, 256>>>(Q, K, V);

    cudaFuncSetAttribute(fa_mma_kernel,
                         cudaFuncAttributeMaxDynamicSharedMemorySize, SMEM_TOTAL);
    dim3 grid(NSEQ/BQ, BATCH);
    fa_mma_kernel<<<grid, NTHR, SMEM_TOTAL>>>(PM, O);
}

// round 8
// speedup vs baseline: 1.2092x; 1.2084x over previous
#include <cuda_runtime.h>
#include <cuda_bf16.h>
#include <cstdint>

// Causal attention B=16, N=2048, D=256 fp32, mma.sync bf16 3-term split.
// R6: warp-specialized producer/consumer.
//   warps 0-3 (S-group): S = Q K^T (16 rows x 64 cols each), exp/mask/lsum,
//     write P(kt) bf16 hi/lo into ping-pong buffer; own K cp.async pipeline.
//   warps 4-7 (PV-group): O += P(kt) V(kt) (16 rows x 256 cols each);
//     own V cp.async pipeline.
//   Sync: mbarriers full[2]/empty[2] (arrive count 128), named bars 5/6
//   for intra-group K/V buffer reuse. 1 S-warp + 1 PV-warp per SMSP.

#define NSEQ  2048
#define DH    256
#define BATCH 16
#define BQ    64
#define BK    64
#define NELEM (BATCH*NSEQ*DH)

__device__ __nv_bfloat16 g_qhi[NELEM];
__device__ __nv_bfloat16 g_qlo[NELEM];
__device__ __nv_bfloat16 g_khi[NELEM];
__device__ __nv_bfloat16 g_klo[NELEM];
__device__ __nv_bfloat16 g_vhi[NELEM];
__device__ __nv_bfloat16 g_vlo[NELEM];

// ---- smem byte offsets ----
#define O_MB   0        // 4 mbarriers: full0,full1,empty0,empty1 (8B each)
#define O_PM   64       // pm[2][64] floats (ping-pong)
#define O_LR   640      // 64 floats row sums
#define O_QHI  1024
#define O_QLO  33792
#define O_KHI  66560
#define O_KLO  99328
#define O_VHI  132096
#define O_VLO  164864
#define O_P0   197632   // P buf: hi at +0 (8KB), lo at +8192; buf stride 16384
#define SMEM_TOTAL 230400

__device__ __forceinline__ uint32_t smem_u32(const void* p){
    uint32_t a; asm("{ .reg .u64 t; cvta.to.shared.u64 t, %1; cvt.u32.u64 %0, t; }":"=r"(a):"l"(p)); return a;
}
__device__ __forceinline__ void ldsm4(uint32_t a, uint32_t r[4]){
    asm volatile("ldmatrix.sync.aligned.m8n8.x4.shared.b16 {%0,%1,%2,%3},[%4];"
                 :"=r"(r[0]),"=r"(r[1]),"=r"(r[2]),"=r"(r[3]):"r"(a));
}
__device__ __forceinline__ void ldsm4t(uint32_t a, uint32_t r[4]){
    asm volatile("ldmatrix.sync.aligned.m8n8.x4.trans.shared.b16 {%0,%1,%2,%3},[%4];"
                 :"=r"(r[0]),"=r"(r[1]),"=r"(r[2]),"=r"(r[3]):"r"(a));
}
__device__ __forceinline__ void mma16816(float c[4], const uint32_t a[4], uint32_t b0, uint32_t b1){
    asm volatile("mma.sync.aligned.m16n8k16.row.col.f32.bf16.bf16.f32 "
                 "{%0,%1,%2,%3},{%4,%5,%6,%7},{%8,%9},{%0,%1,%2,%3};"
                 :"+f"(c[0]),"+f"(c[1]),"+f"(c[2]),"+f"(c[3])
                 :"r"(a[0]),"r"(a[1]),"r"(a[2]),"r"(a[3]),"r"(b0),"r"(b1));
}
__device__ __forceinline__ void cpa16(uint32_t dst, const void* src){
    asm volatile("cp.async.cg.shared.global [%0],[%1],16;"::"r"(dst),"l"(src):"memory");
}
#define CP_COMMIT() asm volatile("cp.async.commit_group;":::"memory")
#define CP_WAIT0()  asm volatile("cp.async.wait_group 0;":::"memory")
#define BARS(id)    asm volatile("bar.sync %0, 128;"::"r"(id):"memory")

#define MB_INIT(a,c) asm volatile("mbarrier.init.shared.b64 [%0], %1;"::"r"((uint32_t)(a)),"r"((uint32_t)(c)):"memory")
#define MB_ARRIVE(a) asm volatile("mbarrier.arrive.shared.b64 _, [%0];"::"r"((uint32_t)(a)):"memory")
#define MB_WAIT(a,ph) do{ uint32_t _m=(uint32_t)(a),_p=(uint32_t)(ph),_d; \
    asm volatile("{ .reg .pred p; mbarrier.try_wait.parity.acquire.cta.shared::cta.b64 p,[%1],%2; selp.b32 %0,1,0,p; }":"=r"(_d):"r"(_m),"r"(_p):"memory"); \
    if(!_d){ asm volatile("{ .reg .pred P1; WL_%=: mbarrier.try_wait.parity.acquire.cta.shared::cta.b64 P1,[%0],%1,0x989680; @P1 bra.uni WD_%=; bra.uni WL_%=; WD_%=: }"::"r"(_m),"r"(_p):"memory"); } }while(0)

__device__ __forceinline__ uint32_t pack2(float a, float b){
    __nv_bfloat162 h; h.x=__float2bfloat16(a); h.y=__float2bfloat16(b);
    return *reinterpret_cast<uint32_t*>(&h);
}
__device__ __forceinline__ uint32_t pack_hi2(float a, float b, float& ra, float& rb){
    __nv_bfloat16 ha=__float2bfloat16(a), hb=__float2bfloat16(b);
    ra = a - __bfloat162float(ha); rb = b - __bfloat162float(hb);
    __nv_bfloat162 h; h.x=ha; h.y=hb;
    return *reinterpret_cast<uint32_t*>(&h);
}

// ---- pass 1: fp32 -> bf16 hi/lo ----
__global__ void cvt_kernel(const float* __restrict__ Q, const float* __restrict__ K,
                           const float* __restrict__ V)
{
    int i = blockIdx.x*blockDim.x + threadIdx.x;
    float4 q = ((const float4*)Q)[i];
    q.x*=0.0625f; q.y*=0.0625f; q.z*=0.0625f; q.w*=0.0625f;
    float l0,l1,l2,l3;
    uint32_t h01,h23;
    h01 = pack_hi2(q.x,q.y,l0,l1); h23 = pack_hi2(q.z,q.w,l2,l3);
    ((uint32_t*)g_qhi)[2*i]=h01; ((uint32_t*)g_qhi)[2*i+1]=h23;
    ((uint32_t*)g_qlo)[2*i]=pack2(l0,l1); ((uint32_t*)g_qlo)[2*i+1]=pack2(l2,l3);
    float4 k = ((const float4*)K)[i];
    h01 = pack_hi2(k.x,k.y,l0,l1); h23 = pack_hi2(k.z,k.w,l2,l3);
    ((uint32_t*)g_khi)[2*i]=h01; ((uint32_t*)g_khi)[2*i+1]=h23;
    ((uint32_t*)g_klo)[2*i]=pack2(l0,l1); ((uint32_t*)g_klo)[2*i+1]=pack2(l2,l3);
    float4 v = ((const float4*)V)[i];
    h01 = pack_hi2(v.x,v.y,l0,l1); h23 = pack_hi2(v.z,v.w,l2,l3);
    ((uint32_t*)g_vhi)[2*i]=h01; ((uint32_t*)g_vhi)[2*i+1]=h23;
    ((uint32_t*)g_vlo)[2*i]=pack2(l0,l1); ((uint32_t*)g_vlo)[2*i+1]=pack2(l2,l3);
}

// cp.async one 64x256 bf16 tile with 128 threads (16 chunks of 16B each)
__device__ __forceinline__ void load_tile128(uint32_t smb, uint32_t off,
                                             const __nv_bfloat16* gsrc, int t)
{
    const char* gs = (const char*)gsrc;
    #pragma unroll
    for (int it=0; it<16; ++it){
        int cid = t + it*128;
        int row = cid >> 5, c = cid & 31;
        uint32_t dst = smb + off + row*512 + (((uint32_t)(c ^ (row&7)))<<4);
        cpa16(dst, gs + row*512 + c*16);
    }
}

__global__ __launch_bounds__(256,1)
void fa_ws_kernel(const int* __restrict__ PMg, float* __restrict__ Og)
{
    extern __shared__ char sm[];
    const uint32_t smb = smem_u32(sm);
    const int tid=threadIdx.x, lane=tid&31, wid=tid>>5;
    const int qt = (int)gridDim.x-1-(int)blockIdx.x;
    const int b  = blockIdx.y;
    const int qbase = qt*BQ;
    const size_t base = (size_t)b*NSEQ*DH;

    const uint32_t mb_full0  = smb + O_MB;
    const uint32_t mb_full1  = smb + O_MB + 8;
    const uint32_t mb_empty0 = smb + O_MB + 16;
    const uint32_t mb_empty1 = smb + O_MB + 24;

    if (tid==0){
        MB_INIT(mb_full0,128); MB_INIT(mb_full1,128);
        MB_INIT(mb_empty0,128); MB_INIT(mb_empty1,128);
    }
    __syncthreads();

    if (wid < 4){
        // ================= S-group (producer) =================
        const int t = tid;           // 0..127
        const int rb = wid;
        // prologue loads: Q + K(0)
        load_tile128(smb, O_QHI, g_qhi + base + (size_t)qbase*DH, t);
        load_tile128(smb, O_QLO, g_qlo + base + (size_t)qbase*DH, t);
        load_tile128(smb, O_KHI, g_khi + base, t);
        load_tile128(smb, O_KLO, g_klo + base, t);
        CP_COMMIT();
        if (t < BK)
            ((float*)(sm+O_PM))[t] = PMg[(size_t)b*NSEQ + t] ? 1.f : 0.f;

        const int rowA = rb*16 + (lane & 15);
        const int ahl  = lane >> 4;
        const int rxa  = rowA & 7;
        const uint32_t aQhi = smb + O_QHI + rowA*512;
        const uint32_t aQlo = smb + O_QLO + rowA*512;

        const int rowB = (lane & 7) + ((lane >> 4) << 3);
        const int bhl  = (lane >> 3) & 1;
        const int rxb  = rowB & 7;
        const uint32_t bKhi = smb + O_KHI + rowB*512;
        const uint32_t bKlo = smb + O_KLO + rowB*512;

        float lsum0=0.f, lsum1=0.f;
        int sep0=0, sep1=0;

        for (int kt=0; kt<=qt; ++kt){
            const int kbase = kt*BK;
            const int bp = kt & 1;

            CP_WAIT0();          // K(kt) (and Q on kt=0) landed for my chunks
            BARS(5);             // visible to all S warps

            // ---- S = Q K^T : 16 rows x 64 cols ----
            float sacc[8][4];
            #pragma unroll
            for (int j=0;j<8;++j){ sacc[j][0]=0.f;sacc[j][1]=0.f;sacc[j][2]=0.f;sacc[j][3]=0.f; }

            for (int ks=0; ks<16; ++ks){
                uint32_t a_hi[4], a_lo[4];
                uint32_t swa = (uint32_t)((ks*2 + ahl) ^ rxa) << 4;
                ldsm4(aQhi + swa, a_hi);
                ldsm4(aQlo + swa, a_lo);
                uint32_t swb = (uint32_t)((ks*2 + bhl) ^ rxb) << 4;
                #pragma unroll
                for (int jp=0; jp<4; ++jp){
                    uint32_t bh[4], bl[4];
                    uint32_t rofs = (uint32_t)(jp*16*512);
                    ldsm4(bKhi + rofs + swb, bh);
                    ldsm4(bKlo + rofs + swb, bl);
                    mma16816(sacc[2*jp],   a_hi, bh[0], bh[1]);
                    mma16816(sacc[2*jp+1], a_hi, bh[2], bh[3]);
                    mma16816(sacc[2*jp],   a_lo, bh[0], bh[1]);
                    mma16816(sacc[2*jp+1], a_lo, bh[2], bh[3]);
                    mma16816(sacc[2*jp],   a_hi, bl[0], bl[1]);
                    mma16816(sacc[2*jp+1], a_hi, bl[2], bl[3]);
                }
            }

            BARS(5);             // all S warps done reading K(kt)

            // ---- issue K(kt+1); refill PM ping-pong ----
            if (kt < qt){
                const size_t nk = base + (size_t)(kbase+BK)*DH;
                load_tile128(smb, O_KHI, g_khi + nk, t);
                load_tile128(smb, O_KLO, g_klo + nk, t);
                CP_COMMIT();
                if (t < BK)
                    ((float*)(sm + O_PM + ((kt+1)&1)*256))[t] =
                        PMg[(size_t)b*NSEQ + kbase + BK + t] ? 1.f : 0.f;
            }

            // ---- epilogue: P = exp(S)*pad*(causal on diag) ----
            const float* pmv = (const float*)(sm + O_PM + bp*256);
            const bool diag = (kt == qt);
            const int r0g = qbase + rb*16 + (lane>>2);
            const int rloc = rb*16 + (lane>>2);
            float rs0=0.f, rs1=0.f;
            uint32_t hA[8], lA[8], hB[8], lB[8];
            #pragma unroll
            for (int j=0;j<8;++j){
                int c0 = j*8 + (lane&3)*2;
                float m0 = pmv[c0], m1 = pmv[c0+1];
                int gc0 = kbase + c0;
                float v0 = __expf(sacc[j][0]) * m0;
                float v1 = __expf(sacc[j][1]) * m1;
                float v2 = __expf(sacc[j][2]) * m0;
                float v3 = __expf(sacc[j][3]) * m1;
                if (diag){
                    if (gc0   > r0g)   v0 = 0.f;
                    if (gc0+1 > r0g)   v1 = 0.f;
                    if (gc0   > r0g+8) v2 = 0.f;
                    if (gc0+1 > r0g+8) v3 = 0.f;
                }
                rs0 += v0 + v1;  rs1 += v2 + v3;
                float l0,l1;
                hA[j]=pack_hi2(v0,v1,l0,l1); lA[j]=pack2(l0,l1);
                hB[j]=pack_hi2(v2,v3,l0,l1); lB[j]=pack2(l0,l1);
            }
            rs0 += __shfl_xor_sync(0xffffffffu, rs0, 1);
            rs0 += __shfl_xor_sync(0xffffffffu, rs0, 2);
            rs1 += __shfl_xor_sync(0xffffffffu, rs1, 1);
            rs1 += __shfl_xor_sync(0xffffffffu, rs1, 2);
            lsum0 += rs0;  lsum1 += rs1;

            // ---- wait P buffer free, write P, signal full ----
            if (kt >= 2){
                if (bp==0){ MB_WAIT(mb_empty0, sep0); sep0^=1; }
                else      { MB_WAIT(mb_empty1, sep1); sep1^=1; }
            }
            {
                char* pb = sm + O_P0 + bp*16384;
                #pragma unroll
                for (int j=0;j<8;++j){
                    uint32_t sw  = (uint32_t)((j ^ (rloc&7))<<4) + (lane&3)*4;
                    uint32_t o0 = rloc*128 + sw;
                    uint32_t o2 = (rloc+8)*128 + sw;
                    *(uint32_t*)(pb + o0)        = hA[j];
                    *(uint32_t*)(pb + 8192 + o0) = lA[j];
                    *(uint32_t*)(pb + o2)        = hB[j];
                    *(uint32_t*)(pb + 8192 + o2) = lB[j];
                }
            }
            if (bp==0) MB_ARRIVE(mb_full0); else MB_ARRIVE(mb_full1);
        }

        // row sums -> smem
        float* lr = (float*)(sm + O_LR);
        const int r0 = rb*16 + (lane>>2);
        if ((lane & 3) == 0){ lr[r0] = lsum0; lr[r0+8] = lsum1; }

    } else {
        // ================= PV-group (consumer) =================
        const int t = tid - 128;      // 0..127
        const int rb = wid - 4;
        load_tile128(smb, O_VHI, g_vhi + base, t);
        load_tile128(smb, O_VLO, g_vlo + base, t);
        CP_COMMIT();

        const int rowA = rb*16 + (lane & 15);
        const int ahl  = lane >> 4;
        const int rxa  = rowA & 7;

        const int rowV = (lane & 7) + (((lane >> 3) & 1) << 3);
        const int vhl  = lane >> 4;
        const int rxv  = rowV & 7;
        const uint32_t bVhi = smb + O_VHI + rowV*512;
        const uint32_t bVlo = smb + O_VLO + rowV*512;

        float o[32][4];
        #pragma unroll
        for (int n=0;n<32;++n){ o[n][0]=0.f;o[n][1]=0.f;o[n][2]=0.f;o[n][3]=0.f; }
        int pfp0=0, pfp1=0;

        for (int kt=0; kt<=qt; ++kt){
            const int bp = kt & 1;
            if (bp==0){ MB_WAIT(mb_full0, pfp0); pfp0^=1; }
            else      { MB_WAIT(mb_full1, pfp1); pfp1^=1; }
            CP_WAIT0();          // V(kt) landed for my chunks
            BARS(6);             // visible to all PV warps

            const uint32_t aPhi = smb + O_P0 + bp*16384 + rowA*128;
            const uint32_t aPlo = aPhi + 8192;

            // ---- O += P V : 16 rows x 256 cols ----
            for (int kks=0; kks<4; ++kks){
                uint32_t pa_hi[4], pa_lo[4];
                uint32_t swp = (uint32_t)((kks*2 + ahl) ^ rxa) << 4;
                ldsm4(aPhi + swp, pa_hi);
                ldsm4(aPlo + swp, pa_lo);
                uint32_t vrow = (uint32_t)((kks*16)*512);
                #pragma unroll
                for (int ncp=0; ncp<16; ++ncp){
                    uint32_t vh[4], vl[4];
                    uint32_t sw = (uint32_t)(((ncp*2 + vhl) ^ rxv) << 4);
                    ldsm4t(bVhi + vrow + sw, vh);
                    ldsm4t(bVlo + vrow + sw, vl);
                    mma16816(o[2*ncp],   pa_hi, vh[0], vh[1]);
                    mma16816(o[2*ncp+1], pa_hi, vh[2], vh[3]);
                    mma16816(o[2*ncp],   pa_lo, vh[0], vh[1]);
                    mma16816(o[2*ncp+1], pa_lo, vh[2], vh[3]);
                    mma16816(o[2*ncp],   pa_hi, vl[0], vl[1]);
                    mma16816(o[2*ncp+1], pa_hi, vl[2], vl[3]);
                }
            }

            if (bp==0) MB_ARRIVE(mb_empty0); else MB_ARRIVE(mb_empty1);
            BARS(6);             // all PV warps done reading V(kt)

            if (kt < qt){
                const size_t nk = base + (size_t)(kt*BK+BK)*DH;
                load_tile128(smb, O_VHI, g_vhi + nk, t);
                load_tile128(smb, O_VLO, g_vlo + nk, t);
                CP_COMMIT();
            }
        }

        __syncthreads();   // join with S-group (lr written)

        const float* lr = (const float*)(sm + O_LR);
        const int r0 = rb*16 + (lane>>2);
        const float inv0 = 1.0f/lr[r0];
        const float inv1 = 1.0f/lr[r0+8];
        float* orow0 = Og + ((size_t)b*NSEQ + qbase + r0)*DH     + (lane&3)*2;
        float* orow1 = Og + ((size_t)b*NSEQ + qbase + r0 + 8)*DH + (lane&3)*2;
        #pragma unroll
        for (int nc=0; nc<32; ++nc){
            float2 w0; w0.x = o[nc][0]*inv0; w0.y = o[nc][1]*inv0;
            float2 w1; w1.x = o[nc][2]*inv1; w1.y = o[nc][3]*inv1;
            *(float2*)(orow0 + nc*8) = w0;
            *(float2*)(orow1 + nc*8) = w1;
        }
        return;
    }

    __syncthreads();   // S-group joins (matches PV-group's __syncthreads)
}

extern "C" void kernel_launch(void* const* d_in, const int* in_sizes, int n_in,
                              void* d_out, int out_size)
{
    const float* Q  = (const float*)d_in[0];
    const float* K  = (const float*)d_in[1];
    const float* V  = (const float*)d_in[2];
    const int*   PM = (const int*)d_in[3];
    float*       O  = (float*)d_out;

    cvt_kernel<<<NELEM/4/256, 256>>>(Q, K, V);

    cudaFuncSetAttribute(fa_ws_kernel,
                         cudaFuncAttributeMaxDynamicSharedMemorySize, SMEM_TOTAL);
    dim3 grid(NSEQ/BQ, BATCH);
    fa_ws_kernel<<<grid, 256, SMEM_TOTAL>>>(PM, O);
}